// round 3
// baseline (speedup 1.0000x reference)
#include <cuda_runtime.h>
#include <cstdint>

// Problem constants
#define NLAYER 8
#define DDIM   768
#define EDIM   1536
#define NSTATE 16
#define CONVK  4
#define DTR    48
#define BB     2
#define LL     2048
#define TT     (BB*LL)          // 4096 tokens
#define E2     (2*EDIM)         // 3072
#define SSMW   (DTR + 2*NSTATE) // 80

typedef unsigned long long ull;

// ---------------- scratch (device globals; no allocation allowed) ----------------
__device__ float g_h  [TT*DDIM];   // residual stream
__device__ float g_hn [TT*DDIM];   // rmsnorm output
__device__ float g_proj[TT*E2];    // in_proj output: [:,0:E)=u, [:,E:2E)=gate
__device__ float g_uc [TT*EDIM];   // conv+silu output
__device__ float g_ssm[TT*SSMW];   // x_proj output (dt_r | B | C)
__device__ float g_dt [TT*EDIM];   // softplus dt
__device__ float g_p  [TT*EDIM];   // exp(dt * A[e,0])
__device__ float g_y  [TT*EDIM];   // scan output * silu(gate)
__device__ float g_a1 [NLAYER*EDIM]; // A[l,e,0] = -exp(A_log[l,e,0])

// ---------------- f32x2 helpers (sm_100+) ----------------
__device__ __forceinline__ ull pack2(float x, float y) {
    ull r;
    asm("mov.b64 %0, {%1, %2};" : "=l"(r) : "r"(__float_as_uint(x)), "r"(__float_as_uint(y)));
    return r;
}
__device__ __forceinline__ ull fma2(ull a, ull b, ull c) {
    ull d;
    asm("fma.rn.f32x2 %0, %1, %2, %3;" : "=l"(d) : "l"(a), "l"(b), "l"(c));
    return d;
}
__device__ __forceinline__ void unpack2(ull v, float& x, float& y) {
    unsigned lo, hi;
    asm("mov.b64 {%0, %1}, %2;" : "=r"(lo), "=r"(hi) : "l"(v));
    x = __uint_as_float(lo); y = __uint_as_float(hi);
}

// ---------------- RMSNorm: one block per token ----------------
__global__ void rmsnorm_kernel(const float* __restrict__ x, const float* __restrict__ w,
                               float* __restrict__ out) {
    const int m = blockIdx.x;
    const float* row = x + (size_t)m * DDIM;
    float s = 0.f;
    for (int i = threadIdx.x; i < DDIM; i += 256) { float v = row[i]; s += v * v; }
    #pragma unroll
    for (int o = 16; o > 0; o >>= 1) s += __shfl_xor_sync(0xffffffffu, s, o);
    __shared__ float ws[8];
    __shared__ float sc;
    int wid = threadIdx.x >> 5, lane = threadIdx.x & 31;
    if (lane == 0) ws[wid] = s;
    __syncthreads();
    if (threadIdx.x == 0) {
        float t = 0.f;
        #pragma unroll
        for (int i = 0; i < 8; i++) t += ws[i];
        sc = rsqrtf(t * (1.f / DDIM) + 1e-5f);
    }
    __syncthreads();
    float k = sc;
    for (int i = threadIdx.x; i < DDIM; i += 256)
        out[(size_t)m * DDIM + i] = row[i] * k * w[i];
}

// ---------------- a1 precompute: A[l,e,0] = -exp(A_log[l,e,0]) ----------------
__global__ void a1_kernel(const float* __restrict__ alog, float* __restrict__ a1) {
    int i = blockIdx.x * blockDim.x + threadIdx.x;
    if (i < NLAYER * EDIM) a1[i] = -__expf(alog[(size_t)i * NSTATE]);
}

// ---------------- Epilogue helper ----------------
// EPI 0: plain store. EPI 1: dt = softplus(v + bias[n]); C=dt; C2 = exp(dt*a1[n]).
// EPI 2: C = resid + v (residual add).
template <int EPI>
__device__ __forceinline__ void store_elem(float* C, float* C2, const float* bias,
                                           const float* a1v, const float* resid,
                                           int m, int n, int N, float v) {
    if (n >= N) return;
    size_t idx = (size_t)m * N + n;
    if (EPI == 0) {
        C[idx] = v;
    } else if (EPI == 1) {
        float xx = v + bias[n];
        float dt = (xx > 15.f) ? xx : log1pf(__expf(xx));
        C[idx] = dt;
        C2[idx] = __expf(dt * a1v[n]);
    } else {
        C[idx] = resid[idx] + v;
    }
}

// ---------------- GEMM NT: C[M,N] = A[M,K] * B[N,K]^T (+epilogue) ----------------
template <int BM, int BN, int BK, int TM, int TN, int EPI>
__global__ void __launch_bounds__((BM / TM) * (BN / TN))
gemm_nt(const float* __restrict__ A, int lda,
        const float* __restrict__ B, int ldb,
        float* __restrict__ C, int M, int N, int Kd,
        const float* __restrict__ bias, float* __restrict__ C2,
        const float* __restrict__ a1v, const float* __restrict__ resid) {
    constexpr int THREADS = (BM / TM) * (BN / TN);
    constexpr int NTN = BN / TN;
    __shared__ __align__(16) float As[BK][BM + 4];
    __shared__ __align__(16) float Bs[BK][BN + 4];
    const int tid = threadIdx.x;
    const int bm = blockIdx.y * BM;
    const int bn = blockIdx.x * BN;
    const int trow = (tid / NTN) * TM;
    const int tcol = (tid % NTN) * TN;

    ull acc2[TM][TN / 2];
    #pragma unroll
    for (int i = 0; i < TM; i++)
        #pragma unroll
        for (int j = 0; j < TN / 2; j++) acc2[i][j] = 0ull;

    constexpr int LA = (BM * BK) / (4 * THREADS);
    constexpr int LB = (BN * BK) / (4 * THREADS);

    for (int k0 = 0; k0 < Kd; k0 += BK) {
        #pragma unroll
        for (int i = 0; i < LA; i++) {
            int idx = tid + i * THREADS;
            int r = idx / (BK / 4);
            int c = (idx % (BK / 4)) * 4;
            float4 v = *reinterpret_cast<const float4*>(A + (size_t)(bm + r) * lda + k0 + c);
            As[c][r] = v.x; As[c + 1][r] = v.y; As[c + 2][r] = v.z; As[c + 3][r] = v.w;
        }
        #pragma unroll
        for (int i = 0; i < LB; i++) {
            int idx = tid + i * THREADS;
            int r = idx / (BK / 4);
            int c = (idx % (BK / 4)) * 4;
            float4 v = make_float4(0.f, 0.f, 0.f, 0.f);
            if (bn + r < N)
                v = *reinterpret_cast<const float4*>(B + (size_t)(bn + r) * ldb + k0 + c);
            Bs[c][r] = v.x; Bs[c + 1][r] = v.y; Bs[c + 2][r] = v.z; Bs[c + 3][r] = v.w;
        }
        __syncthreads();
        #pragma unroll
        for (int kk = 0; kk < BK; kk++) {
            float ar[TM];
            #pragma unroll
            for (int i = 0; i < TM; i += 4)
                *reinterpret_cast<float4*>(&ar[i]) =
                    *reinterpret_cast<const float4*>(&As[kk][trow + i]);
            ull b2[TN / 2];
            const ull* bp = reinterpret_cast<const ull*>(&Bs[kk][tcol]);
            #pragma unroll
            for (int j = 0; j < TN / 2; j++) b2[j] = bp[j];
            #pragma unroll
            for (int i = 0; i < TM; i++) {
                ull a2 = pack2(ar[i], ar[i]);
                #pragma unroll
                for (int j = 0; j < TN / 2; j++) acc2[i][j] = fma2(a2, b2[j], acc2[i][j]);
            }
        }
        __syncthreads();
    }
    #pragma unroll
    for (int i = 0; i < TM; i++) {
        int m = bm + trow + i;
        #pragma unroll
        for (int j = 0; j < TN / 2; j++) {
            float c0, c1;
            unpack2(acc2[i][j], c0, c1);
            int n0 = bn + tcol + 2 * j;
            store_elem<EPI>(C, C2, bias, a1v, resid, m, n0, N, c0);
            store_elem<EPI>(C, C2, bias, a1v, resid, m, n0 + 1, N, c1);
        }
    }
}

// ---------------- causal depthwise conv (K=4) + SiLU ----------------
__global__ void conv_silu_kernel(const float* __restrict__ proj, const float* __restrict__ cw,
                                 const float* __restrict__ cb, float* __restrict__ out) {
    int idx = blockIdx.x * blockDim.x + threadIdx.x;
    if (idx >= TT * EDIM) return;
    int e = idx % EDIM;
    int m = idx / EDIM;
    int l = m & (LL - 1);
    float acc = cb[e];
    #pragma unroll
    for (int k = 0; k < CONVK; k++) {
        int li = l - 3 + k;
        if (li >= 0) acc += proj[(size_t)(m - 3 + k) * E2 + e] * cw[e * CONVK + k];
    }
    out[idx] = acc / (1.f + __expf(-acc));
}

// ---------------- selective scan (+ D skip + silu(gate) multiply) ----------------
__global__ void scan_kernel(const float* __restrict__ dt, const float* __restrict__ pex,
                            const float* __restrict__ uc, const float* __restrict__ ssm,
                            const float* __restrict__ proj, const float* __restrict__ alog,
                            const float* __restrict__ dsk, float* __restrict__ y_out) {
    __shared__ float sB[64][NSTATE];
    __shared__ float sC[64][NSTATE];
    const int e = blockIdx.x * 128 + threadIdx.x;
    const int b = blockIdx.y;
    const int base = b * LL;

    float Aar[NSTATE];
    #pragma unroll
    for (int n = 0; n < NSTATE; n++) Aar[n] = -__expf(alog[(size_t)e * NSTATE + n]);
    bool structured = true;
    #pragma unroll
    for (int n = 1; n < NSTATE; n++)
        structured = structured &&
            (fabsf(Aar[n] - (float)(n + 1) * Aar[0]) <= 1e-4f * fabsf(Aar[n]) + 1e-7f);
    const float Dp = dsk[e];

    float st[NSTATE];
    #pragma unroll
    for (int n = 0; n < NSTATE; n++) st[n] = 0.f;

    for (int t0 = 0; t0 < LL; t0 += 64) {
        for (int i = threadIdx.x; i < 64 * 32; i += 128) {
            int r = i >> 5, c = i & 31;
            float v = ssm[(size_t)(base + t0 + r) * SSMW + DTR + c];
            if (c < NSTATE) sB[r][c] = v; else sC[r][c - NSTATE] = v;
        }
        __syncthreads();
        for (int tt = 0; tt < 64; tt++) {
            size_t row = (size_t)(base + t0 + tt);
            float dtv = dt[row * EDIM + e];
            float uv  = uc[row * EDIM + e];
            float dtu = dtv * uv;
            float y0 = 0.f, y1 = 0.f, y2 = 0.f, y3 = 0.f;
            if (structured) {
                float p = pex[row * EDIM + e];
                float pw[NSTATE];
                pw[0] = p;            pw[1] = p * p;
                pw[2] = pw[1] * p;    pw[3] = pw[1] * pw[1];
                pw[4] = pw[3] * p;    pw[5] = pw[3] * pw[1];
                pw[6] = pw[3] * pw[2];pw[7] = pw[3] * pw[3];
                pw[8] = pw[7] * p;    pw[9] = pw[7] * pw[1];
                pw[10]= pw[7] * pw[2];pw[11]= pw[7] * pw[3];
                pw[12]= pw[7] * pw[4];pw[13]= pw[7] * pw[5];
                pw[14]= pw[7] * pw[6];pw[15]= pw[7] * pw[7];
                #pragma unroll
                for (int n = 0; n < NSTATE; n++) {
                    st[n] = st[n] * pw[n] + dtu * sB[tt][n];
                    float yv = st[n] * sC[tt][n];
                    if ((n & 3) == 0) y0 += yv;
                    else if ((n & 3) == 1) y1 += yv;
                    else if ((n & 3) == 2) y2 += yv;
                    else y3 += yv;
                }
            } else {
                #pragma unroll
                for (int n = 0; n < NSTATE; n++) {
                    float dA = __expf(dtv * Aar[n]);
                    st[n] = st[n] * dA + dtu * sB[tt][n];
                    float yv = st[n] * sC[tt][n];
                    if ((n & 3) == 0) y0 += yv;
                    else if ((n & 3) == 1) y1 += yv;
                    else if ((n & 3) == 2) y2 += yv;
                    else y3 += yv;
                }
            }
            float g = proj[row * E2 + EDIM + e];
            float sig = 1.f / (1.f + __expf(-g));
            y_out[row * EDIM + e] = ((y0 + y1) + (y2 + y3) + uv * Dp) * (g * sig);
        }
        __syncthreads();
    }
}

// ---------------- host driver (graph-capturable; no sync, no alloc) ----------------
extern "C" void kernel_launch(void* const* d_in, const int* in_sizes, int n_in,
                              void* d_out, int out_size) {
    const float* x      = (const float*)d_in[0];
    const float* norm_w = (const float*)d_in[1];
    const float* in_w   = (const float*)d_in[2];
    const float* conv_w = (const float*)d_in[3];
    const float* conv_b = (const float*)d_in[4];
    const float* x_w    = (const float*)d_in[5];
    const float* dt_w   = (const float*)d_in[6];
    const float* dt_b   = (const float*)d_in[7];
    const float* alog   = (const float*)d_in[8];
    const float* dsk    = (const float*)d_in[9];
    const float* out_w  = (const float*)d_in[10];
    const float* fn_w   = (const float*)d_in[11];

    float *g_h_p, *g_hn_p, *g_proj_p, *g_uc_p, *g_ssm_p, *g_dt_p, *g_p_p, *g_y_p, *g_a1_p;
    cudaGetSymbolAddress((void**)&g_h_p, g_h);
    cudaGetSymbolAddress((void**)&g_hn_p, g_hn);
    cudaGetSymbolAddress((void**)&g_proj_p, g_proj);
    cudaGetSymbolAddress((void**)&g_uc_p, g_uc);
    cudaGetSymbolAddress((void**)&g_ssm_p, g_ssm);
    cudaGetSymbolAddress((void**)&g_dt_p, g_dt);
    cudaGetSymbolAddress((void**)&g_p_p, g_p);
    cudaGetSymbolAddress((void**)&g_y_p, g_y);
    cudaGetSymbolAddress((void**)&g_a1_p, g_a1);

    a1_kernel<<<(NLAYER * EDIM + 255) / 256, 256>>>(alog, g_a1_p);

    for (int l = 0; l < NLAYER; l++) {
        const float* hin = l ? (const float*)g_h_p : x;

        rmsnorm_kernel<<<TT, 256>>>(hin, norm_w + (size_t)l * DDIM, g_hn_p);

        gemm_nt<128, 128, 16, 8, 8, 0><<<dim3(E2 / 128, TT / 128), 256>>>(
            g_hn_p, DDIM, in_w + (size_t)l * E2 * DDIM, DDIM,
            g_proj_p, TT, E2, DDIM, nullptr, nullptr, nullptr, nullptr);

        conv_silu_kernel<<<(TT * EDIM) / 256, 256>>>(
            g_proj_p, conv_w + (size_t)l * EDIM * CONVK, conv_b + (size_t)l * EDIM, g_uc_p);

        gemm_nt<64, 128, 16, 4, 8, 0><<<dim3(1, TT / 64), 256>>>(
            g_uc_p, EDIM, x_w + (size_t)l * SSMW * EDIM, EDIM,
            g_ssm_p, TT, SSMW, EDIM, nullptr, nullptr, nullptr, nullptr);

        gemm_nt<128, 128, 16, 8, 8, 1><<<dim3(EDIM / 128, TT / 128), 256>>>(
            g_ssm_p, SSMW, dt_w + (size_t)l * EDIM * DTR, DTR,
            g_dt_p, TT, EDIM, DTR, dt_b + (size_t)l * EDIM, g_p_p,
            g_a1_p + (size_t)l * EDIM, nullptr);

        scan_kernel<<<dim3(EDIM / 128, BB), 128>>>(
            g_dt_p, g_p_p, g_uc_p, g_ssm_p, g_proj_p,
            alog + (size_t)l * EDIM * NSTATE, dsk + (size_t)l * EDIM, g_y_p);

        gemm_nt<128, 128, 16, 8, 8, 2><<<dim3(DDIM / 128, TT / 128), 256>>>(
            g_y_p, EDIM, out_w + (size_t)l * DDIM * EDIM, EDIM,
            g_h_p, TT, DDIM, EDIM, nullptr, nullptr, nullptr, hin);
    }

    rmsnorm_kernel<<<TT, 256>>>(g_h_p, fn_w, (float*)d_out);
}

// round 4
// speedup vs baseline: 1.0559x; 1.0559x over previous
#include <cuda_runtime.h>
#include <cstdint>

// Problem constants
#define NLAYER 8
#define DDIM   768
#define EDIM   1536
#define NSTATE 16
#define CONVK  4
#define DTR    48
#define BB     2
#define LL     2048
#define TT     (BB*LL)          // 4096 tokens
#define E2     (2*EDIM)         // 3072
#define SSMW   (DTR + 2*NSTATE) // 80

typedef unsigned long long ull;

// ---------------- scratch (device globals; no allocation allowed) ----------------
__device__ float g_h  [TT*DDIM];   // residual stream
__device__ float g_hn [TT*DDIM];   // rmsnorm output
__device__ float g_proj[TT*E2];    // in_proj output: [:,0:E)=u, [:,E:2E)=gate
__device__ float g_uc [TT*EDIM];   // conv+silu output
__device__ float g_ssm[TT*SSMW];   // x_proj output (dt_r | B | C)
__device__ float g_dt [TT*EDIM];   // softplus dt
__device__ float g_p  [TT*EDIM];   // exp(dt * A[e,0])
__device__ float g_y  [TT*EDIM];   // scan output * silu(gate)
__device__ float g_a1 [NLAYER*EDIM]; // A[l,e,0] = -exp(A_log[l,e,0])

// ---------------- f32x2 helpers (sm_100+) ----------------
__device__ __forceinline__ ull pack2(float x, float y) {
    ull r;
    asm("mov.b64 %0, {%1, %2};" : "=l"(r) : "r"(__float_as_uint(x)), "r"(__float_as_uint(y)));
    return r;
}
__device__ __forceinline__ ull fma2(ull a, ull b, ull c) {
    ull d;
    asm("fma.rn.f32x2 %0, %1, %2, %3;" : "=l"(d) : "l"(a), "l"(b), "l"(c));
    return d;
}
__device__ __forceinline__ void unpack2(ull v, float& x, float& y) {
    unsigned lo, hi;
    asm("mov.b64 {%0, %1}, %2;" : "=r"(lo), "=r"(hi) : "l"(v));
    x = __uint_as_float(lo); y = __uint_as_float(hi);
}

// ---------------- RMSNorm: one block per token ----------------
__global__ void rmsnorm_kernel(const float* __restrict__ x, const float* __restrict__ w,
                               float* __restrict__ out) {
    const int m = blockIdx.x;
    const float* row = x + (size_t)m * DDIM;
    float s = 0.f;
    for (int i = threadIdx.x; i < DDIM; i += 256) { float v = row[i]; s += v * v; }
    #pragma unroll
    for (int o = 16; o > 0; o >>= 1) s += __shfl_xor_sync(0xffffffffu, s, o);
    __shared__ float ws[8];
    __shared__ float sc;
    int wid = threadIdx.x >> 5, lane = threadIdx.x & 31;
    if (lane == 0) ws[wid] = s;
    __syncthreads();
    if (threadIdx.x == 0) {
        float t = 0.f;
        #pragma unroll
        for (int i = 0; i < 8; i++) t += ws[i];
        sc = rsqrtf(t * (1.f / DDIM) + 1e-5f);
    }
    __syncthreads();
    float k = sc;
    for (int i = threadIdx.x; i < DDIM; i += 256)
        out[(size_t)m * DDIM + i] = row[i] * k * w[i];
}

// ---------------- a1 precompute: A[l,e,0] = -exp(A_log[l,e,0]) ----------------
__global__ void a1_kernel(const float* __restrict__ alog, float* __restrict__ a1) {
    int i = blockIdx.x * blockDim.x + threadIdx.x;
    if (i < NLAYER * EDIM) a1[i] = -__expf(alog[(size_t)i * NSTATE]);
}

// ---------------- Epilogue helper ----------------
template <int EPI>
__device__ __forceinline__ void store_elem(float* C, float* C2, const float* bias,
                                           const float* a1v, const float* resid,
                                           int m, int n, int N, float v) {
    if (n >= N) return;
    size_t idx = (size_t)m * N + n;
    if (EPI == 0) {
        C[idx] = v;
    } else if (EPI == 1) {
        float xx = v + bias[n];
        float dt = (xx > 15.f) ? xx : log1pf(__expf(xx));
        C[idx] = dt;
        C2[idx] = __expf(dt * a1v[n]);
    } else {
        C[idx] = resid[idx] + v;
    }
}

// ---------------- GEMM NT: C[M,N] = A[M,K] * B[N,K]^T (+epilogue) ----------------
// Thread column mapping: g = tid % NTN owns columns [4g,4g+4) and [BN/2+4g, BN/2+4g+4).
// This makes every B-fragment read a conflict-free LDS.128 (banks 4g..4g+3 per phase),
// replacing the old stride-8 mapping whose reads were 8-way bank conflicted.
template <int BM, int BN, int BK, int TM, int TN, int EPI>
__global__ void __launch_bounds__((BM / TM) * (BN / TN))
gemm_nt(const float* __restrict__ A, int lda,
        const float* __restrict__ B, int ldb,
        float* __restrict__ C, int M, int N, int Kd,
        const float* __restrict__ bias, float* __restrict__ C2,
        const float* __restrict__ a1v, const float* __restrict__ resid) {
    constexpr int THREADS = (BM / TM) * (BN / TN);
    constexpr int NTN = BN / TN;   // 16
    constexpr int HALF = BN / 2;
    static_assert(TN == 8, "column mapping assumes TN=8");
    __shared__ __align__(16) float As[BK][BM + 4];
    __shared__ __align__(16) float Bs[BK][BN + 4];
    const int tid = threadIdx.x;
    const int bm = blockIdx.y * BM;
    const int bn = blockIdx.x * BN;
    const int g = tid % NTN;
    const int trow = (tid / NTN) * TM;

    ull acc2[TM][4];
    #pragma unroll
    for (int i = 0; i < TM; i++)
        #pragma unroll
        for (int j = 0; j < 4; j++) acc2[i][j] = 0ull;

    constexpr int LA = (BM * BK) / (4 * THREADS);
    constexpr int LB = (BN * BK) / (4 * THREADS);

    for (int k0 = 0; k0 < Kd; k0 += BK) {
        #pragma unroll
        for (int i = 0; i < LA; i++) {
            int idx = tid + i * THREADS;
            int r = idx / (BK / 4);
            int c = (idx % (BK / 4)) * 4;
            float4 v = *reinterpret_cast<const float4*>(A + (size_t)(bm + r) * lda + k0 + c);
            As[c][r] = v.x; As[c + 1][r] = v.y; As[c + 2][r] = v.z; As[c + 3][r] = v.w;
        }
        #pragma unroll
        for (int i = 0; i < LB; i++) {
            int idx = tid + i * THREADS;
            int r = idx / (BK / 4);
            int c = (idx % (BK / 4)) * 4;
            float4 v = make_float4(0.f, 0.f, 0.f, 0.f);
            if (bn + r < N)
                v = *reinterpret_cast<const float4*>(B + (size_t)(bn + r) * ldb + k0 + c);
            Bs[c][r] = v.x; Bs[c + 1][r] = v.y; Bs[c + 2][r] = v.z; Bs[c + 3][r] = v.w;
        }
        __syncthreads();
        #pragma unroll
        for (int kk = 0; kk < BK; kk++) {
            float ar[TM];
            #pragma unroll
            for (int i = 0; i < TM; i += 4)
                *reinterpret_cast<float4*>(&ar[i]) =
                    *reinterpret_cast<const float4*>(&As[kk][trow + i]);
            ull b2[4];
            {
                const ull* bp0 = reinterpret_cast<const ull*>(&Bs[kk][4 * g]);
                const ull* bp1 = reinterpret_cast<const ull*>(&Bs[kk][HALF + 4 * g]);
                b2[0] = bp0[0]; b2[1] = bp0[1];
                b2[2] = bp1[0]; b2[3] = bp1[1];
            }
            #pragma unroll
            for (int i = 0; i < TM; i++) {
                ull a2 = pack2(ar[i], ar[i]);
                #pragma unroll
                for (int j = 0; j < 4; j++) acc2[i][j] = fma2(a2, b2[j], acc2[i][j]);
            }
        }
        __syncthreads();
    }
    #pragma unroll
    for (int i = 0; i < TM; i++) {
        int m = bm + trow + i;
        #pragma unroll
        for (int j = 0; j < 4; j++) {
            float c0, c1;
            unpack2(acc2[i][j], c0, c1);
            int h = j >> 1, jj = j & 1;
            int n0 = bn + h * HALF + 4 * g + 2 * jj;
            store_elem<EPI>(C, C2, bias, a1v, resid, m, n0, N, c0);
            store_elem<EPI>(C, C2, bias, a1v, resid, m, n0 + 1, N, c1);
        }
    }
}

// ---------------- causal depthwise conv (K=4) + SiLU ----------------
__global__ void conv_silu_kernel(const float* __restrict__ proj, const float* __restrict__ cw,
                                 const float* __restrict__ cb, float* __restrict__ out) {
    int idx = blockIdx.x * blockDim.x + threadIdx.x;
    if (idx >= TT * EDIM) return;
    int e = idx % EDIM;
    int m = idx / EDIM;
    int l = m & (LL - 1);
    float acc = cb[e];
    #pragma unroll
    for (int k = 0; k < CONVK; k++) {
        int li = l - 3 + k;
        if (li >= 0) acc += proj[(size_t)(m - 3 + k) * E2 + e] * cw[e * CONVK + k];
    }
    out[idx] = acc / (1.f + __expf(-acc));
}

// ---------------- selective scan (+ D skip + silu(gate) multiply) ----------------
__global__ void scan_kernel(const float* __restrict__ dt, const float* __restrict__ pex,
                            const float* __restrict__ uc, const float* __restrict__ ssm,
                            const float* __restrict__ proj, const float* __restrict__ alog,
                            const float* __restrict__ dsk, float* __restrict__ y_out) {
    __shared__ float sB[64][NSTATE];
    __shared__ float sC[64][NSTATE];
    const int e = blockIdx.x * 128 + threadIdx.x;
    const int b = blockIdx.y;
    const int base = b * LL;

    float Aar[NSTATE];
    #pragma unroll
    for (int n = 0; n < NSTATE; n++) Aar[n] = -__expf(alog[(size_t)e * NSTATE + n]);
    bool structured = true;
    #pragma unroll
    for (int n = 1; n < NSTATE; n++)
        structured = structured &&
            (fabsf(Aar[n] - (float)(n + 1) * Aar[0]) <= 1e-4f * fabsf(Aar[n]) + 1e-7f);
    const float Dp = dsk[e];

    float st[NSTATE];
    #pragma unroll
    for (int n = 0; n < NSTATE; n++) st[n] = 0.f;

    for (int t0 = 0; t0 < LL; t0 += 64) {
        for (int i = threadIdx.x; i < 64 * 32; i += 128) {
            int r = i >> 5, c = i & 31;
            float v = ssm[(size_t)(base + t0 + r) * SSMW + DTR + c];
            if (c < NSTATE) sB[r][c] = v; else sC[r][c - NSTATE] = v;
        }
        __syncthreads();
        for (int tt = 0; tt < 64; tt++) {
            size_t row = (size_t)(base + t0 + tt);
            float dtv = dt[row * EDIM + e];
            float uv  = uc[row * EDIM + e];
            float dtu = dtv * uv;
            float y0 = 0.f, y1 = 0.f, y2 = 0.f, y3 = 0.f;
            if (structured) {
                float p = pex[row * EDIM + e];
                float pw[NSTATE];
                pw[0] = p;            pw[1] = p * p;
                pw[2] = pw[1] * p;    pw[3] = pw[1] * pw[1];
                pw[4] = pw[3] * p;    pw[5] = pw[3] * pw[1];
                pw[6] = pw[3] * pw[2];pw[7] = pw[3] * pw[3];
                pw[8] = pw[7] * p;    pw[9] = pw[7] * pw[1];
                pw[10]= pw[7] * pw[2];pw[11]= pw[7] * pw[3];
                pw[12]= pw[7] * pw[4];pw[13]= pw[7] * pw[5];
                pw[14]= pw[7] * pw[6];pw[15]= pw[7] * pw[7];
                #pragma unroll
                for (int n = 0; n < NSTATE; n++) {
                    st[n] = st[n] * pw[n] + dtu * sB[tt][n];
                    float yv = st[n] * sC[tt][n];
                    if ((n & 3) == 0) y0 += yv;
                    else if ((n & 3) == 1) y1 += yv;
                    else if ((n & 3) == 2) y2 += yv;
                    else y3 += yv;
                }
            } else {
                #pragma unroll
                for (int n = 0; n < NSTATE; n++) {
                    float dA = __expf(dtv * Aar[n]);
                    st[n] = st[n] * dA + dtu * sB[tt][n];
                    float yv = st[n] * sC[tt][n];
                    if ((n & 3) == 0) y0 += yv;
                    else if ((n & 3) == 1) y1 += yv;
                    else if ((n & 3) == 2) y2 += yv;
                    else y3 += yv;
                }
            }
            float gte = proj[row * E2 + EDIM + e];
            float sig = 1.f / (1.f + __expf(-gte));
            y_out[row * EDIM + e] = ((y0 + y1) + (y2 + y3) + uv * Dp) * (gte * sig);
        }
        __syncthreads();
    }
}

// ---------------- host driver (graph-capturable; no sync, no alloc) ----------------
extern "C" void kernel_launch(void* const* d_in, const int* in_sizes, int n_in,
                              void* d_out, int out_size) {
    const float* x      = (const float*)d_in[0];
    const float* norm_w = (const float*)d_in[1];
    const float* in_w   = (const float*)d_in[2];
    const float* conv_w = (const float*)d_in[3];
    const float* conv_b = (const float*)d_in[4];
    const float* x_w    = (const float*)d_in[5];
    const float* dt_w   = (const float*)d_in[6];
    const float* dt_b   = (const float*)d_in[7];
    const float* alog   = (const float*)d_in[8];
    const float* dsk    = (const float*)d_in[9];
    const float* out_w  = (const float*)d_in[10];
    const float* fn_w   = (const float*)d_in[11];

    float *g_h_p, *g_hn_p, *g_proj_p, *g_uc_p, *g_ssm_p, *g_dt_p, *g_p_p, *g_y_p, *g_a1_p;
    cudaGetSymbolAddress((void**)&g_h_p, g_h);
    cudaGetSymbolAddress((void**)&g_hn_p, g_hn);
    cudaGetSymbolAddress((void**)&g_proj_p, g_proj);
    cudaGetSymbolAddress((void**)&g_uc_p, g_uc);
    cudaGetSymbolAddress((void**)&g_ssm_p, g_ssm);
    cudaGetSymbolAddress((void**)&g_dt_p, g_dt);
    cudaGetSymbolAddress((void**)&g_p_p, g_p);
    cudaGetSymbolAddress((void**)&g_y_p, g_y);
    cudaGetSymbolAddress((void**)&g_a1_p, g_a1);

    a1_kernel<<<(NLAYER * EDIM + 255) / 256, 256>>>(alog, g_a1_p);

    for (int l = 0; l < NLAYER; l++) {
        const float* hin = l ? (const float*)g_h_p : x;

        rmsnorm_kernel<<<TT, 256>>>(hin, norm_w + (size_t)l * DDIM, g_hn_p);

        gemm_nt<128, 128, 32, 8, 8, 0><<<dim3(E2 / 128, TT / 128), 256>>>(
            g_hn_p, DDIM, in_w + (size_t)l * E2 * DDIM, DDIM,
            g_proj_p, TT, E2, DDIM, nullptr, nullptr, nullptr, nullptr);

        conv_silu_kernel<<<(TT * EDIM) / 256, 256>>>(
            g_proj_p, conv_w + (size_t)l * EDIM * CONVK, conv_b + (size_t)l * EDIM, g_uc_p);

        gemm_nt<64, 128, 32, 4, 8, 0><<<dim3(1, TT / 64), 256>>>(
            g_uc_p, EDIM, x_w + (size_t)l * SSMW * EDIM, EDIM,
            g_ssm_p, TT, SSMW, EDIM, nullptr, nullptr, nullptr, nullptr);

        gemm_nt<128, 128, 16, 8, 8, 1><<<dim3(EDIM / 128, TT / 128), 256>>>(
            g_ssm_p, SSMW, dt_w + (size_t)l * EDIM * DTR, DTR,
            g_dt_p, TT, EDIM, DTR, dt_b + (size_t)l * EDIM, g_p_p,
            g_a1_p + (size_t)l * EDIM, nullptr);

        scan_kernel<<<dim3(EDIM / 128, BB), 128>>>(
            g_dt_p, g_p_p, g_uc_p, g_ssm_p, g_proj_p,
            alog + (size_t)l * EDIM * NSTATE, dsk + (size_t)l * EDIM, g_y_p);

        gemm_nt<128, 128, 32, 8, 8, 2><<<dim3(DDIM / 128, TT / 128), 256>>>(
            g_y_p, EDIM, out_w + (size_t)l * DDIM * EDIM, EDIM,
            g_h_p, TT, DDIM, EDIM, nullptr, nullptr, nullptr, hin);
    }

    rmsnorm_kernel<<<TT, 256>>>(g_h_p, fn_w, (float*)d_out);
}